// round 13
// baseline (speedup 1.0000x reference)
#include <cuda_runtime.h>

#define F 1024
#define KDIM 4096            // 4 * F
#define SPLITK 8
#define KCHUNK 512           // KDIM / SPLITK
#define NTILES 32            // KCHUNK / 16

#define GEMM_BLOCKS 512      // (M/32=4) x (N/64=16) x SPLITK=8
#define N_SRC_MEM1 511
#define N_SRC_MEM2 508
#define N_SRC_INP  512
#define FAN 4
#define SCATTER_BASE GEMM_BLOCKS                                        // 512
#define NONCOMP_BLOCKS ((N_SRC_MEM1 + N_SRC_MEM2 + N_SRC_INP) * FAN)    // 6124
#define COMP_BASE (SCATTER_BASE + NONCOMP_BLOCKS)                       // 6636
#define COMP_BLOCKS (128 * FAN)                                         // 512
#define TOTAL_BLOCKS (COMP_BASE + COMP_BLOCKS)                          // 7148

// Scratch (no cudaMalloc allowed)
__device__ float g_part[SPLITK][128][F];     // 4 MB split-K partials
__device__ unsigned g_flag;                  // GEMM done counter

// ---------------------------------------------------------------------------
// One fused kernel, ENTIRELY sized for 8 blocks/SM (32 regs, 12KB smem):
// the scatter's HBM-write throughput is MLP-limited, so occupancy is the
// first-order knob (R12: occ 45% -> only 62% DRAM; standalone 91% -> 74%).
//   blocks [0,512)       : split-K fp32 GEMM part[kz] = X[128,4096]@W[4096,1024]
//                          32x64 tile, BK=16, 2x4 microtile, double-buffered
//                          smem + register prefetch. Low-reg by design; its
//                          efficiency is irrelevant (off critical path).
//   blocks [512,6636)    : scatter-copy of rows NOT depending on comp.
//   blocks [6636,7148)   : comp rows (grid tail): wait on g_flag, combine
//                          split-K partials + bias inline, scatter.
// Wait cannot deadlock: GEMM blocks occupy the lowest indices -> wave 1.
// Scatter map (inversion of the gather; each source row read ONCE):
//   memory[r], r=1..511   -> (b, r-b-1)       for b = 0..min(r-1,127)
//   memory[516+d], d<508  -> (b, 512+d-4b)    for b = 0..(d>>2) [<=126]
//   inputs[j],  j=0..511  -> (b, 1020-4b+j)   for b = (j>>2)..127
//   comp[c],    c=0..127  -> (b, 511-b+c)     for b = c..127
// ---------------------------------------------------------------------------
__global__ __launch_bounds__(256, 8) void OSAR_fused(
    const float* __restrict__ inputs, const float* __restrict__ memory,
    const float* __restrict__ W, const float* __restrict__ bias,
    float* __restrict__ out)
{
    const int bid = blockIdx.x;
    const int tid = threadIdx.x;

    __shared__ float As[2][16][32];   // As[buf][k][m]  (A transposed)  4KB
    __shared__ float Bs[2][16][64];   // Bs[buf][k][n]                  8KB

    // ================= GEMM blocks =================
    if (bid < GEMM_BLOCKS) {
        const int kz = bid & 7;
        const int bn = (bid >> 3) & 15;
        const int bm = bid >> 7;          // 0..3

        const float* Xb = memory + 512 * F + bm * 32 * KDIM + kz * KCHUNK;
        const float* Wb = W + (size_t)kz * KCHUNK * F + bn * 64;

        // A load: threads 0..127 each load one float4 (32 rows x 4 k-slots)
        const int ar  = (tid & 127) >> 2, ak = tid & 3;
        const bool aload = tid < 128;
        // B load: every thread one float4 (16 k-rows x 16 n-slots)
        const int brk = tid >> 4, bn4 = tid & 15;
        // microtile: 16x16 thread grid, 2 rows x 4 cols each
        const int ty  = tid >> 4, tx  = tid & 15;

        float acc[2][4] = {};

        float4 av, bv;
        if (aload) av = *(const float4*)(Xb + ar * KDIM + ak * 4);
        bv = *(const float4*)(Wb + (size_t)brk * F + bn4 * 4);
        if (aload) {
            As[0][ak * 4 + 0][ar] = av.x;
            As[0][ak * 4 + 1][ar] = av.y;
            As[0][ak * 4 + 2][ar] = av.z;
            As[0][ak * 4 + 3][ar] = av.w;
        }
        *(float4*)&Bs[0][brk][bn4 * 4] = bv;
        __syncthreads();

        int cur = 0;
        for (int t = 0; t < NTILES; t++) {
            if (t + 1 < NTILES) {   // prefetch next tile into registers
                if (aload)
                    av = *(const float4*)(Xb + ar * KDIM + (t + 1) * 16 + ak * 4);
                bv = *(const float4*)(Wb + (size_t)((t + 1) * 16 + brk) * F + bn4 * 4);
            }
#pragma unroll
            for (int k = 0; k < 16; k++) {
                float a0 = As[cur][k][ty * 2];
                float a1 = As[cur][k][ty * 2 + 1];
                float4 b = *(float4*)&Bs[cur][k][tx * 4];
                acc[0][0] += a0 * b.x; acc[0][1] += a0 * b.y;
                acc[0][2] += a0 * b.z; acc[0][3] += a0 * b.w;
                acc[1][0] += a1 * b.x; acc[1][1] += a1 * b.y;
                acc[1][2] += a1 * b.z; acc[1][3] += a1 * b.w;
            }
            if (t + 1 < NTILES) {
                int nxt = cur ^ 1;
                if (aload) {
                    As[nxt][ak * 4 + 0][ar] = av.x;
                    As[nxt][ak * 4 + 1][ar] = av.y;
                    As[nxt][ak * 4 + 2][ar] = av.z;
                    As[nxt][ak * 4 + 3][ar] = av.w;
                }
                *(float4*)&Bs[nxt][brk][bn4 * 4] = bv;
            }
            __syncthreads();
            cur ^= 1;
        }

        float* dst = &g_part[kz][bm * 32 + ty * 2][bn * 64 + tx * 4];
        *(float4*)dst       = make_float4(acc[0][0], acc[0][1], acc[0][2], acc[0][3]);
        *(float4*)(dst + F) = make_float4(acc[1][0], acc[1][1], acc[1][2], acc[1][3]);

        __syncthreads();
        if (tid == 0) { __threadfence(); atomicAdd(&g_flag, 1u); }
        return;
    }

    float4* out4 = (float4*)out;

    // ================= non-comp scatter blocks =================
    if (bid < COMP_BASE) {
        const int cid = bid - SCATTER_BASE;
        const int sid = cid >> 2;
        const int y   = cid & 3;

        if (sid < N_SRC_MEM1) {
            const int r = sid + 1;                        // memory row 1..511
            const int cnt = min(r, 128);
            const float4 v = ((const float4*)(memory + (size_t)r * F))[tid];
            for (int b = y; b < cnt; b += FAN)
                out4[(size_t)(b * 1024 + (r - b - 1)) * 256 + tid] = v;
        } else if (sid < N_SRC_MEM1 + N_SRC_MEM2) {
            const int d = sid - N_SRC_MEM1;               // 0..507
            const int cnt = min(d >> 2, 126) + 1;
            const float4 v = ((const float4*)(memory + (size_t)(516 + d) * F))[tid];
            for (int b = y; b < cnt; b += FAN)
                out4[(size_t)(b * 1024 + 512 + d - 4 * b) * 256 + tid] = v;
        } else {
            const int j = sid - (N_SRC_MEM1 + N_SRC_MEM2);   // 0..511
            const int b0 = j >> 2;
            const float4 v = ((const float4*)(inputs + (size_t)j * F))[tid];
            for (int b = b0 + y; b < 128; b += FAN)
                out4[(size_t)(b * 1024 + 1020 - 4 * b + j) * 256 + tid] = v;
        }
        return;
    }

    // ================= comp scatter blocks (grid tail) =================
    {
        const int cid = bid - COMP_BASE;
        const int c = cid >> 2;       // comp row 0..127
        const int y = cid & 3;

        if (tid == 0) {
            volatile unsigned* f = &g_flag;
            while (*f < GEMM_BLOCKS) __nanosleep(128);
            __threadfence();
        }
        __syncthreads();

        float4 v = ((const float4*)bias)[tid];
#pragma unroll
        for (int z = 0; z < SPLITK; z++) {
            float4 p = ((const float4*)g_part[z][c])[tid];
            v.x += p.x; v.y += p.y; v.z += p.z; v.w += p.w;
        }
        for (int b = c + y; b < 128; b += FAN)
            out4[(size_t)(b * 1024 + 511 - b + c) * 256 + tid] = v;
    }
}

// ---------------------------------------------------------------------------
extern "C" void kernel_launch(void* const* d_in, const int* in_sizes, int n_in,
                              void* d_out, int out_size) {
    const float* inputs = (const float*)d_in[0];   // (128, 4, 1024)
    const float* memory = (const float*)d_in[1];   // (1024, 1024)
    const float* kern   = (const float*)d_in[2];   // (4, 1024, 1024)
    const float* bias   = (const float*)d_in[3];   // (1024,)
    float* out = (float*)d_out;                    // (128, 1024, 1024)

    void* flagAddr = nullptr;
    cudaGetSymbolAddress(&flagAddr, g_flag);
    cudaMemsetAsync(flagAddr, 0, sizeof(unsigned));

    OSAR_fused<<<TOTAL_BLOCKS, 256>>>(inputs, memory, kern, bias, out);
}

// round 14
// speedup vs baseline: 1.3671x; 1.3671x over previous
#include <cuda_runtime.h>

#define F 1024
#define KDIM 4096            // 4 * F
#define SPLITK 8
#define KCHUNK 512           // KDIM / SPLITK
#define NTILES 32            // KCHUNK / 16

#define GEMM_BLOCKS 256      // (N/64=16) x (M/64=2) x SPLITK=8
#define N_SRC_MEM1 511
#define N_SRC_MEM2 508
#define N_SRC_INP  512
#define FAN 2                // dest-fanout split per source row
#define SCATTER_BASE GEMM_BLOCKS                                        // 256
#define NONCOMP_BLOCKS ((N_SRC_MEM1 + N_SRC_MEM2 + N_SRC_INP) * FAN)    // 3062
#define COMP_BASE (SCATTER_BASE + NONCOMP_BLOCKS)                       // 3318
#define COMP_BLOCKS (128 * FAN)                                         // 256
#define TOTAL_BLOCKS (COMP_BASE + COMP_BLOCKS)                          // 3574

// Scratch (no cudaMalloc allowed)
__device__ float g_part[SPLITK][128][F];     // 4 MB split-K partials
__device__ unsigned g_flag;                  // GEMM done counter

// smem views over one 16KB block (GEMM tiles / scatter staging share it)
#define AS(buf,k,m) sh[(buf)*1024 + (k)*64 + (m)]
#define BS(buf,k,n) sh[2048 + (buf)*1024 + (k)*64 + (n)]

// One 4KB bulk store: smem row -> global row (TMA path, single instruction).
__device__ __forceinline__ void bulk_store_row(const float* gdst, unsigned saddr) {
    asm volatile("cp.async.bulk.global.shared::cta.bulk_group [%0], [%1], %2;"
                 :: "l"(gdst), "r"(saddr), "r"(4096) : "memory");
}

// ---------------------------------------------------------------------------
// One fused kernel. The scatter is STG-issue-floor bound when done with
// per-thread stores (R8/R12 evidence: ~5.8TB/s ceiling independent of occ);
// here each 4KB destination row is written by ONE cp.async.bulk (UTMASTG),
// eliminating the issue floor. GEMM keeps the proven fat config (64 regs) —
// scatter no longer needs issue bandwidth or occupancy.
//   blocks [0,256)       : split-K fp32 GEMM part[kz]=X[128,4096]@W[4096,1024]
//                          64x64 tile, BK=16, 4x4 microtile, double-buffered.
//   blocks [256,3318)    : non-comp scatter (stage row in smem, bulk-store).
//   blocks [3318,3574)   : comp rows (tail): wait flag, combine split-K
//                          partials + bias, stage, bulk-store.
// Scatter map (inversion of the gather; each source row read ONCE):
//   memory[r], r=1..511   -> (b, r-b-1)       for b = 0..min(r-1,127)
//   memory[516+d], d<508  -> (b, 512+d-4b)    for b = 0..(d>>2) [<=126]
//   inputs[j],  j=0..511  -> (b, 1020-4b+j)   for b = (j>>2)..127
//   comp[c],    c=0..127  -> (b, 511-b+c)     for b = c..127
// ---------------------------------------------------------------------------
__global__ __launch_bounds__(256) void OSAR_fused(
    const float* __restrict__ inputs, const float* __restrict__ memory,
    const float* __restrict__ W, const float* __restrict__ bias,
    float* __restrict__ out)
{
    __shared__ float sh[4096];        // 16KB

    const int bid = blockIdx.x;
    const int tid = threadIdx.x;

    // ================= GEMM blocks =================
    if (bid < GEMM_BLOCKS) {
        const int kz = bid & 7;
        const int bn = (bid >> 3) & 15;
        const int bm = bid >> 7;

        const float* Xb = memory + 512 * F + bm * 64 * KDIM + kz * KCHUNK;
        const float* Wb = W + (size_t)kz * KCHUNK * F + bn * 64;

        const int ar  = tid >> 2, ak  = tid & 3;    // A load: m-row, k float4 slot
        const int brk = tid >> 4, bn4 = tid & 15;   // B load: k-row, n float4 slot
        const int ty  = tid >> 4, tx  = tid & 15;   // 16x16 microtile grid

        float acc[4][4] = {};

        float4 av = *(const float4*)(Xb + ar * KDIM + ak * 4);
        float4 bv = *(const float4*)(Wb + (size_t)brk * F + bn4 * 4);
        AS(0, ak * 4 + 0, ar) = av.x;
        AS(0, ak * 4 + 1, ar) = av.y;
        AS(0, ak * 4 + 2, ar) = av.z;
        AS(0, ak * 4 + 3, ar) = av.w;
        *(float4*)&BS(0, brk, bn4 * 4) = bv;
        __syncthreads();

        int cur = 0;
        for (int t = 0; t < NTILES; t++) {
            if (t + 1 < NTILES) {   // prefetch next tile into registers
                av = *(const float4*)(Xb + ar * KDIM + (t + 1) * 16 + ak * 4);
                bv = *(const float4*)(Wb + (size_t)((t + 1) * 16 + brk) * F + bn4 * 4);
            }
#pragma unroll
            for (int k = 0; k < 16; k++) {
                float4 a = *(float4*)&AS(cur, k, ty * 4);
                float4 b = *(float4*)&BS(cur, k, tx * 4);
                acc[0][0] += a.x * b.x; acc[0][1] += a.x * b.y;
                acc[0][2] += a.x * b.z; acc[0][3] += a.x * b.w;
                acc[1][0] += a.y * b.x; acc[1][1] += a.y * b.y;
                acc[1][2] += a.y * b.z; acc[1][3] += a.y * b.w;
                acc[2][0] += a.z * b.x; acc[2][1] += a.z * b.y;
                acc[2][2] += a.z * b.z; acc[2][3] += a.z * b.w;
                acc[3][0] += a.w * b.x; acc[3][1] += a.w * b.y;
                acc[3][2] += a.w * b.z; acc[3][3] += a.w * b.w;
            }
            if (t + 1 < NTILES) {
                int nxt = cur ^ 1;
                AS(nxt, ak * 4 + 0, ar) = av.x;
                AS(nxt, ak * 4 + 1, ar) = av.y;
                AS(nxt, ak * 4 + 2, ar) = av.z;
                AS(nxt, ak * 4 + 3, ar) = av.w;
                *(float4*)&BS(nxt, brk, bn4 * 4) = bv;
            }
            __syncthreads();
            cur ^= 1;
        }

        float* dst = &g_part[kz][bm * 64 + ty * 4][bn * 64 + tx * 4];
#pragma unroll
        for (int i = 0; i < 4; i++)
            *(float4*)(dst + (size_t)i * F) =
                make_float4(acc[i][0], acc[i][1], acc[i][2], acc[i][3]);

        __syncthreads();
        if (tid == 0) { __threadfence(); atomicAdd(&g_flag, 1u); }
        return;
    }

    const int lane = tid & 31;
    const int wid  = tid >> 5;
    const unsigned saddr = (unsigned)__cvta_generic_to_shared(sh);

    // ================= non-comp scatter blocks =================
    if (bid < COMP_BASE) {
        const int cid = bid - SCATTER_BASE;
        const int sid = cid >> 1;          // source row id
        const int y   = cid & 1;           // fanout half

        int mode, p0, cnt;                 // dest row = f(mode, p0, b)
        const float* src;
        if (sid < N_SRC_MEM1) {
            const int r = sid + 1;                         // memory row 1..511
            src = memory + (size_t)r * F;
            mode = 0; p0 = r; cnt = min(r, 128);
        } else if (sid < N_SRC_MEM1 + N_SRC_MEM2) {
            const int d = sid - N_SRC_MEM1;                // 0..507
            src = memory + (size_t)(516 + d) * F;
            mode = 1; p0 = d; cnt = min(d >> 2, 126) + 1;
        } else {
            const int j = sid - (N_SRC_MEM1 + N_SRC_MEM2); // 0..511
            src = inputs + (size_t)j * F;
            mode = 2; p0 = j; cnt = 128;
        }

        ((float4*)sh)[tid] = ((const float4*)src)[tid];    // stage 4KB
        __syncthreads();

        if (lane == 0) {
            asm volatile("fence.proxy.async.shared::cta;" ::: "memory");
            const int b0 = (mode == 2) ? ((p0 >> 2) + y) : y;
            for (int b = b0 + wid * FAN; b < cnt; b += 8 * FAN) {
                int m;
                if (mode == 0)      m = p0 - b - 1;
                else if (mode == 1) m = 512 + p0 - 4 * b;
                else                m = 1020 - 4 * b + p0;
                bulk_store_row(out + ((size_t)b * 1024 + m) * F, saddr);
            }
            asm volatile("cp.async.bulk.commit_group;" ::: "memory");
            asm volatile("cp.async.bulk.wait_group 0;" ::: "memory");
        }
        return;
    }

    // ================= comp scatter blocks (grid tail) =================
    {
        const int cid = bid - COMP_BASE;
        const int c = cid >> 1;            // comp row 0..127
        const int y = cid & 1;

        if (tid == 0) {
            volatile unsigned* f = &g_flag;
            while (*f < GEMM_BLOCKS) __nanosleep(128);
            __threadfence();
        }
        __syncthreads();

        float4 v = ((const float4*)bias)[tid];
#pragma unroll
        for (int z = 0; z < SPLITK; z++) {
            float4 p = ((const float4*)g_part[z][c])[tid];
            v.x += p.x; v.y += p.y; v.z += p.z; v.w += p.w;
        }
        ((float4*)sh)[tid] = v;            // stage combined comp row
        __syncthreads();

        if (lane == 0) {
            asm volatile("fence.proxy.async.shared::cta;" ::: "memory");
            for (int b = c + y + wid * FAN; b < 128; b += 8 * FAN)
                bulk_store_row(out + ((size_t)b * 1024 + 511 - b + c) * F, saddr);
            asm volatile("cp.async.bulk.commit_group;" ::: "memory");
            asm volatile("cp.async.bulk.wait_group 0;" ::: "memory");
        }
    }
}

// ---------------------------------------------------------------------------
extern "C" void kernel_launch(void* const* d_in, const int* in_sizes, int n_in,
                              void* d_out, int out_size) {
    const float* inputs = (const float*)d_in[0];   // (128, 4, 1024)
    const float* memory = (const float*)d_in[1];   // (1024, 1024)
    const float* kern   = (const float*)d_in[2];   // (4, 1024, 1024)
    const float* bias   = (const float*)d_in[3];   // (1024,)
    float* out = (float*)d_out;                    // (128, 1024, 1024)

    void* flagAddr = nullptr;
    cudaGetSymbolAddress(&flagAddr, g_flag);
    cudaMemsetAsync(flagAddr, 0, sizeof(unsigned));

    OSAR_fused<<<TOTAL_BLOCKS, 256>>>(inputs, memory, kern, bias, out);
}

// round 15
// speedup vs baseline: 1.3960x; 1.0212x over previous
#include <cuda_runtime.h>

#define F 1024
#define KDIM 4096            // 4 * F
#define SPLITK 16
#define KCHUNK 256           // KDIM / SPLITK
#define NTILES 16            // KCHUNK / 16

#define GEMM_BLOCKS 128      // (N/128=8) x SPLITK=16, M=128 full per block
#define N_SRC_MEM1 511
#define N_SRC_MEM2 508
#define N_SRC_INP  512
#define FAN 2                // dest-fanout split per source row
#define SCATTER_BASE GEMM_BLOCKS                                        // 128
#define NONCOMP_BLOCKS ((N_SRC_MEM1 + N_SRC_MEM2 + N_SRC_INP) * FAN)    // 3062
#define COMP_BASE (SCATTER_BASE + NONCOMP_BLOCKS)                       // 3190
#define COMP_BLOCKS (128 * FAN)                                         // 256
#define TOTAL_BLOCKS (COMP_BASE + COMP_BLOCKS)                          // 3446

// Scratch (no cudaMalloc allowed)
__device__ float g_part[SPLITK][128][F];     // 8 MB split-K partials
__device__ unsigned g_flag;                  // GEMM done counter

// smem: 32KB shared between GEMM tiles and scatter staging (4KB used there)
#define AS(buf,k,m) sh[(buf)*2048 + (k)*128 + (m)]
#define BS(buf,k,n) sh[4096 + (buf)*2048 + (k)*128 + (n)]

// One 4KB bulk store: smem row -> global row (TMA path, single instruction).
__device__ __forceinline__ void bulk_store_row(const float* gdst, unsigned saddr) {
    asm volatile("cp.async.bulk.global.shared::cta.bulk_group [%0], [%1], %2;"
                 :: "l"(gdst), "r"(saddr), "r"(4096) : "memory");
}

// ---------------------------------------------------------------------------
// One fused kernel.
//   blocks [0,128)       : split-K fp32 GEMM part[kz]=X[128,4096]@W[4096,1024]
//                          128x128 tile (M full), BK=16, 8x8 microtile,
//                          double-buffered + register prefetch. High intensity
//                          (64 FMA / 4 LDS.128) -> short wallclock, and only
//                          128 SMs touched -> minimal scatter interference.
//   blocks [128,3190)    : non-comp scatter (stage 4KB row, TMA bulk stores).
//   blocks [3190,3446)   : comp rows (tail): wait flag, combine 16 split-K
//                          partials + bias, stage, bulk-store.
// Wait cannot deadlock: GEMM blocks occupy the lowest indices -> wave 1.
// Scatter map (inversion of the gather; each source row read ONCE):
//   memory[r], r=1..511   -> (b, r-b-1)       for b = 0..min(r-1,127)
//   memory[516+d], d<508  -> (b, 512+d-4b)    for b = 0..(d>>2) [<=126]
//   inputs[j],  j=0..511  -> (b, 1020-4b+j)   for b = (j>>2)..127
//   comp[c],    c=0..127  -> (b, 511-b+c)     for b = c..127
// ---------------------------------------------------------------------------
__global__ __launch_bounds__(256) void OSAR_fused(
    const float* __restrict__ inputs, const float* __restrict__ memory,
    const float* __restrict__ W, const float* __restrict__ bias,
    float* __restrict__ out)
{
    __shared__ float sh[8192];        // 32KB

    const int bid = blockIdx.x;
    const int tid = threadIdx.x;

    // ================= GEMM blocks =================
    if (bid < GEMM_BLOCKS) {
        const int kz = bid & 15;          // K chunk
        const int bn = bid >> 4;          // 0..7 (N tile of 128)

        const float* Xb = memory + 512 * F + kz * KCHUNK;
        const float* Wb = W + (size_t)(kz * KCHUNK) * F + bn * 128;

        // A load: 2 float4/thread; idx=tid*2+i -> row=idx>>2 (0..127), slot=idx&3
        // B load: 2 float4/thread; idx=tid*2+i -> krow=idx>>5 (0..15), ns=idx&31
        const int ty = tid >> 4, tx = tid & 15;   // 16x16 grid, 8x8 microtile

        float acc[8][8] = {};
        float4 av[2], bv[2];

#pragma unroll
        for (int i = 0; i < 2; i++) {
            int idx = tid * 2 + i;
            av[i] = *(const float4*)(Xb + (size_t)(idx >> 2) * KDIM + (idx & 3) * 4);
            bv[i] = *(const float4*)(Wb + (size_t)(idx >> 5) * F + (idx & 31) * 4);
        }
#pragma unroll
        for (int i = 0; i < 2; i++) {
            int idx = tid * 2 + i;
            int row = idx >> 2, slot = idx & 3;
            AS(0, slot * 4 + 0, row) = av[i].x;
            AS(0, slot * 4 + 1, row) = av[i].y;
            AS(0, slot * 4 + 2, row) = av[i].z;
            AS(0, slot * 4 + 3, row) = av[i].w;
            *(float4*)&BS(0, idx >> 5, (idx & 31) * 4) = bv[i];
        }
        __syncthreads();

        int cur = 0;
        for (int t = 0; t < NTILES; t++) {
            if (t + 1 < NTILES) {   // prefetch next tile into registers
#pragma unroll
                for (int i = 0; i < 2; i++) {
                    int idx = tid * 2 + i;
                    av[i] = *(const float4*)(Xb + (size_t)(idx >> 2) * KDIM +
                                             (t + 1) * 16 + (idx & 3) * 4);
                    bv[i] = *(const float4*)(Wb + (size_t)((t + 1) * 16 + (idx >> 5)) * F +
                                             (idx & 31) * 4);
                }
            }
#pragma unroll
            for (int k = 0; k < 16; k++) {
                float4 a0 = *(float4*)&AS(cur, k, ty * 8);
                float4 a1 = *(float4*)&AS(cur, k, ty * 8 + 4);
                float4 b0 = *(float4*)&BS(cur, k, tx * 8);
                float4 b1 = *(float4*)&BS(cur, k, tx * 8 + 4);
                float ar[8] = {a0.x, a0.y, a0.z, a0.w, a1.x, a1.y, a1.z, a1.w};
                float br[8] = {b0.x, b0.y, b0.z, b0.w, b1.x, b1.y, b1.z, b1.w};
#pragma unroll
                for (int r = 0; r < 8; r++)
#pragma unroll
                    for (int c = 0; c < 8; c++)
                        acc[r][c] += ar[r] * br[c];
            }
            if (t + 1 < NTILES) {
                int nxt = cur ^ 1;
#pragma unroll
                for (int i = 0; i < 2; i++) {
                    int idx = tid * 2 + i;
                    int row = idx >> 2, slot = idx & 3;
                    AS(nxt, slot * 4 + 0, row) = av[i].x;
                    AS(nxt, slot * 4 + 1, row) = av[i].y;
                    AS(nxt, slot * 4 + 2, row) = av[i].z;
                    AS(nxt, slot * 4 + 3, row) = av[i].w;
                    *(float4*)&BS(nxt, idx >> 5, (idx & 31) * 4) = bv[i];
                }
            }
            __syncthreads();
            cur ^= 1;
        }

        float* dst = &g_part[kz][ty * 8][bn * 128 + tx * 8];
#pragma unroll
        for (int r = 0; r < 8; r++) {
            *(float4*)(dst + (size_t)r * F) =
                make_float4(acc[r][0], acc[r][1], acc[r][2], acc[r][3]);
            *(float4*)(dst + (size_t)r * F + 4) =
                make_float4(acc[r][4], acc[r][5], acc[r][6], acc[r][7]);
        }

        __syncthreads();
        if (tid == 0) { __threadfence(); atomicAdd(&g_flag, 1u); }
        return;
    }

    const int lane = tid & 31;
    const int wid  = tid >> 5;
    const unsigned saddr = (unsigned)__cvta_generic_to_shared(sh);

    // ================= non-comp scatter blocks =================
    if (bid < COMP_BASE) {
        const int cid = bid - SCATTER_BASE;
        const int sid = cid >> 1;          // source row id
        const int y   = cid & 1;           // fanout half

        int mode, p0, cnt;                 // dest row = f(mode, p0, b)
        const float* src;
        if (sid < N_SRC_MEM1) {
            const int r = sid + 1;                         // memory row 1..511
            src = memory + (size_t)r * F;
            mode = 0; p0 = r; cnt = min(r, 128);
        } else if (sid < N_SRC_MEM1 + N_SRC_MEM2) {
            const int d = sid - N_SRC_MEM1;                // 0..507
            src = memory + (size_t)(516 + d) * F;
            mode = 1; p0 = d; cnt = min(d >> 2, 126) + 1;
        } else {
            const int j = sid - (N_SRC_MEM1 + N_SRC_MEM2); // 0..511
            src = inputs + (size_t)j * F;
            mode = 2; p0 = j; cnt = 128;
        }

        ((float4*)sh)[tid] = ((const float4*)src)[tid];    // stage 4KB
        __syncthreads();

        if (lane == 0) {
            asm volatile("fence.proxy.async.shared::cta;" ::: "memory");
            const int b0 = (mode == 2) ? ((p0 >> 2) + y) : y;
            for (int b = b0 + wid * FAN; b < cnt; b += 8 * FAN) {
                int m;
                if (mode == 0)      m = p0 - b - 1;
                else if (mode == 1) m = 512 + p0 - 4 * b;
                else                m = 1020 - 4 * b + p0;
                bulk_store_row(out + ((size_t)b * 1024 + m) * F, saddr);
            }
            asm volatile("cp.async.bulk.commit_group;" ::: "memory");
            asm volatile("cp.async.bulk.wait_group 0;" ::: "memory");
        }
        return;
    }

    // ================= comp scatter blocks (grid tail) =================
    {
        const int cid = bid - COMP_BASE;
        const int c = cid >> 1;            // comp row 0..127
        const int y = cid & 1;

        if (tid == 0) {
            volatile unsigned* f = &g_flag;
            while (*f < GEMM_BLOCKS) __nanosleep(128);
            __threadfence();
        }
        __syncthreads();

        float4 v = ((const float4*)bias)[tid];
#pragma unroll
        for (int z = 0; z < SPLITK; z++) {
            float4 p = ((const float4*)g_part[z][c])[tid];
            v.x += p.x; v.y += p.y; v.z += p.z; v.w += p.w;
        }
        ((float4*)sh)[tid] = v;            // stage combined comp row
        __syncthreads();

        if (lane == 0) {
            asm volatile("fence.proxy.async.shared::cta;" ::: "memory");
            for (int b = c + y + wid * FAN; b < 128; b += 8 * FAN)
                bulk_store_row(out + ((size_t)b * 1024 + 511 - b + c) * F, saddr);
            asm volatile("cp.async.bulk.commit_group;" ::: "memory");
            asm volatile("cp.async.bulk.wait_group 0;" ::: "memory");
        }
    }
}

// ---------------------------------------------------------------------------
extern "C" void kernel_launch(void* const* d_in, const int* in_sizes, int n_in,
                              void* d_out, int out_size) {
    const float* inputs = (const float*)d_in[0];   // (128, 4, 1024)
    const float* memory = (const float*)d_in[1];   // (1024, 1024)
    const float* kern   = (const float*)d_in[2];   // (4, 1024, 1024)
    const float* bias   = (const float*)d_in[3];   // (1024,)
    float* out = (float*)d_out;                    // (128, 1024, 1024)

    void* flagAddr = nullptr;
    cudaGetSymbolAddress(&flagAddr, g_flag);
    cudaMemsetAsync(flagAddr, 0, sizeof(unsigned));

    OSAR_fused<<<TOTAL_BLOCKS, 256>>>(inputs, memory, kern, bias, out);
}